// round 14
// baseline (speedup 1.0000x reference)
#include <cuda_runtime.h>
#include <cstdint>

// ---------------------------------------------------------------------------
// Q[n,m] = P[n] + R[m] + sum_h (w2[h]/2)|a[n,h] + b[m,h]|
// Rows pre-scaled by |w|/2:  (w/2)|a+b| = sign(w) * |a' + b'|.
// h-space sign-partitioned: positives (rank 0..pc-1) then negatives.
// Precompute: features in ORIGINAL h order (coalesced W1 loads), permutation
// applied via popc-rank + per-warp smem scatter.
// qmain: segmented FADD2 loop, ping-pong double-buffered LDS across h2 at
// constant occupancy (4 CTAs/SM, regs budgeted to fit the 128 cap).
// ---------------------------------------------------------------------------

#define NMAX 2048
#define HID  64
#define HP   32   // h pairs

__device__ unsigned long long g_aT[HP][NMAX];  // scaled, permuted job rows
__device__ unsigned long long g_bT[HP][NMAX];  // scaled, permuted machine rows
__device__ float g_P[NMAX];
__device__ float g_R[NMAX];
__device__ int g_K1;           // # pure-positive pairs
__device__ int g_mix;          // 1 if a mixed (+,-) pair exists at slot K1

__device__ __forceinline__ unsigned long long pack2(float lo, float hi) {
    return (unsigned long long)__float_as_uint(lo) |
           ((unsigned long long)__float_as_uint(hi) << 32);
}

// rank of original index h within the sign partition (positives first).
__device__ __forceinline__ int rank_of(int h, unsigned bal0, unsigned bal1,
                                       int pc) {
    bool pos = (h < 32) ? ((bal0 >> h) & 1) : ((bal1 >> (h - 32)) & 1);
    unsigned b0 = pos ? bal0 : ~bal0;
    unsigned b1 = pos ? bal1 : ~bal1;
    int r = (h < 32) ? __popc(b0 & ((1u << h) - 1u))
                     : __popc(b0) + __popc(b1 & ((1u << (h - 32)) - 1u));
    return (pos ? 0 : pc) + r;
}

// ---------------------------------------------------------------------------
// Precompute: one warp per row; lane = h-pair (original order).
// Scatter scaled values through per-warp smem staging to apply permutation.
// ---------------------------------------------------------------------------
__global__ void __launch_bounds__(256) precompute_kernel(
    const float* __restrict__ job, const float* __restrict__ mac,
    const float* __restrict__ gvec,
    const float* __restrict__ Wj, const float* __restrict__ bj,
    const float* __restrict__ Wm, const float* __restrict__ bm,
    const float* __restrict__ Wg, const float* __restrict__ bg,
    const float* __restrict__ W1, const float* __restrict__ b1,
    const float* __restrict__ W2, const float* __restrict__ b2,
    int n, int m)
{
    __shared__ __align__(8) float stage[8][64];

    const int wrp  = threadIdx.x >> 5;
    const int row  = blockIdx.x * 8 + wrp;
    const int lane = threadIdx.x & 31;
    if (row >= n + m) return;   // row is warp-uniform: whole warp exits

    // Sign partition (identical in every warp, deterministic).
    const float w_lo = W2[lane];
    const float w_hi = W2[lane + 32];
    const unsigned bal0 = __ballot_sync(0xFFFFFFFFu, w_lo >= 0.0f);
    const unsigned bal1 = __ballot_sync(0xFFFFFFFFu, w_hi >= 0.0f);
    const int pc = __popc(bal0) + __popc(bal1);

    if (blockIdx.x == 0 && threadIdx.x == 0) {
        g_K1  = pc >> 1;
        g_mix = pc & 1;
    }

    const float2 w2p = *(const float2*)&W2[2 * lane];  // own original pair

    float f0, f1;   // features for ORIGINAL h = 2*lane, 2*lane+1
    if (row < n) {
        const float x = job[row];
        f0 = 0.0f; f1 = 0.0f;
        #pragma unroll
        for (int j = 0; j < 16; ++j) {
            float f = fmaxf(fmaf(x, Wj[j], bj[j]), 0.0f);
            float2 w = *(const float2*)&W1[j * HID + 2 * lane];
            f0 = fmaf(f, w.x, f0);
            f1 = fmaf(f, w.y, f1);
        }
    } else {
        const int mm = row - n;
        const float x = mac[mm];
        float2 bb = *(const float2*)&b1[2 * lane];
        f0 = bb.x; f1 = bb.y;
        #pragma unroll
        for (int k = 0; k < 8; ++k) {
            float gf = bg[k];
            #pragma unroll
            for (int i = 0; i < 8; ++i)
                gf = fmaf(gvec[i], Wg[i * 8 + k], gf);
            gf = fmaxf(gf, 0.0f);
            float2 w = *(const float2*)&W1[(32 + k) * HID + 2 * lane];
            f0 = fmaf(gf, w.x, f0);
            f1 = fmaf(gf, w.y, f1);
        }
        #pragma unroll
        for (int j = 0; j < 16; ++j) {
            float f = fmaxf(fmaf(x, Wm[j], bm[j]), 0.0f);
            float2 w = *(const float2*)&W1[(16 + j) * HID + 2 * lane];
            f0 = fmaf(f, w.x, f0);
            f1 = fmaf(f, w.y, f1);
        }
    }

    // Rank-1 term (permutation-invariant, original order).
    float s = f0 * (0.5f * w2p.x) + f1 * (0.5f * w2p.y);
    #pragma unroll
    for (int d = 16; d > 0; d >>= 1)
        s += __shfl_xor_sync(0xFFFFFFFFu, s, d);

    // Scatter scaled values to permuted slots via smem staging.
    const int r0 = rank_of(2 * lane,     bal0, bal1, pc);
    const int r1 = rank_of(2 * lane + 1, bal0, bal1, pc);
    stage[wrp][r0] = f0 * (0.5f * fabsf(w2p.x));
    stage[wrp][r1] = f1 * (0.5f * fabsf(w2p.y));
    __syncwarp();
    const float2 v = *(const float2*)&stage[wrp][2 * lane];
    const unsigned long long packed = pack2(v.x, v.y);

    if (row < n) {
        g_aT[lane][row] = packed;
        if (lane == 0) g_P[row] = s + b2[0];
    } else {
        g_bT[lane][row - n] = packed;
        if (lane == 0) g_R[row - n] = s;
    }
}

// ---------------------------------------------------------------------------
// Steps. abs/neg fold into the FADD2 source operand modifier.
// ---------------------------------------------------------------------------
__device__ __forceinline__ void stepP(unsigned long long& acc,
                                      unsigned long long a,
                                      unsigned long long b)
{
    asm("{\n\t"
        ".reg .b64 t;\n\t"
        ".reg .f32 lo, hi;\n\t"
        "add.rn.f32x2 t, %1, %2;\n\t"
        "mov.b64 {lo, hi}, t;\n\t"
        "abs.f32 lo, lo;\n\t"
        "abs.f32 hi, hi;\n\t"
        "mov.b64 t, {lo, hi};\n\t"
        "add.rn.f32x2 %0, %0, t;\n\t"
        "}"
        : "+l"(acc) : "l"(a), "l"(b));
}

__device__ __forceinline__ void stepN(unsigned long long& acc,
                                      unsigned long long a,
                                      unsigned long long b)
{
    asm("{\n\t"
        ".reg .b64 t;\n\t"
        ".reg .f32 lo, hi;\n\t"
        "add.rn.f32x2 t, %1, %2;\n\t"
        "mov.b64 {lo, hi}, t;\n\t"
        "abs.f32 lo, lo;\n\t"
        "abs.f32 hi, hi;\n\t"
        "neg.f32 lo, lo;\n\t"
        "neg.f32 hi, hi;\n\t"
        "mov.b64 t, {lo, hi};\n\t"
        "add.rn.f32x2 %0, %0, t;\n\t"
        "}"
        : "+l"(acc) : "l"(a), "l"(b));
}

__device__ __forceinline__ void stepM(unsigned long long& acc,
                                      unsigned long long a,
                                      unsigned long long b,
                                      unsigned long long sv)
{
    asm("{\n\t"
        ".reg .b64 t;\n\t"
        ".reg .f32 lo, hi;\n\t"
        "add.rn.f32x2 t, %1, %2;\n\t"
        "mov.b64 {lo, hi}, t;\n\t"
        "abs.f32 lo, lo;\n\t"
        "abs.f32 hi, hi;\n\t"
        "mov.b64 t, {lo, hi};\n\t"
        "fma.rn.f32x2 %0, t, %3, %0;\n\t"
        "}"
        : "+l"(acc) : "l"(a), "l"(b), "l"(sv));
}

// ---------------------------------------------------------------------------
// qmain helpers: buffered load + 32-step math block.
// ---------------------------------------------------------------------------
__device__ __forceinline__ void tile_load(
    const unsigned long long (*sA)[64], const unsigned long long (*sB)[64],
    int h2, int n0, int m0, ulonglong2 (&A)[4], ulonglong2 (&B)[2])
{
    #pragma unroll
    for (int i = 0; i < 4; ++i)
        A[i] = *(const ulonglong2*)&sA[h2][n0 + 2 * i];
    #pragma unroll
    for (int j = 0; j < 2; ++j)
        B[j] = *(const ulonglong2*)&sB[h2][m0 + 2 * j];
}

template<int SGN>
__device__ __forceinline__ void tile_math(
    unsigned long long (&acc)[8][4],
    const ulonglong2 (&A)[4], const ulonglong2 (&B)[2])
{
    unsigned long long Aa[8] = {A[0].x, A[0].y, A[1].x, A[1].y,
                                A[2].x, A[2].y, A[3].x, A[3].y};
    unsigned long long Bb[4] = {B[0].x, B[0].y, B[1].x, B[1].y};
    #pragma unroll
    for (int i = 0; i < 8; ++i)
        #pragma unroll
        for (int j = 0; j < 4; ++j) {
            if (SGN > 0) stepP(acc[i][j], Aa[i], Bb[j]);
            else         stepN(acc[i][j], Aa[i], Bb[j]);
        }
}

// Ping-pong pipelined segment [s, e): load next h2 before current math.
template<int SGN>
__device__ __forceinline__ void pipe_segment(
    unsigned long long (&acc)[8][4],
    const unsigned long long (*sA)[64], const unsigned long long (*sB)[64],
    int s, int e, int n0, int m0)
{
    ulonglong2 A0[4], B0[2], A1[4], B1[2];
    int i = s;
    if (i < e) tile_load(sA, sB, i, n0, m0, A0, B0);
    for (; i + 1 < e; i += 2) {
        tile_load(sA, sB, i + 1, n0, m0, A1, B1);
        tile_math<SGN>(acc, A0, B0);
        if (i + 2 < e) tile_load(sA, sB, i + 2, n0, m0, A0, B0);
        tile_math<SGN>(acc, A1, B1);
    }
    if (i < e) tile_math<SGN>(acc, A0, B0);
}

// ---------------------------------------------------------------------------
// Main kernel: 128 threads, 64x64 tile, 8n x 4m per thread, 4 CTAs/SM.
// ---------------------------------------------------------------------------
__global__ void __launch_bounds__(128, 4) qmain_kernel(
    float* __restrict__ out, int N, int M)
{
    __shared__ unsigned long long sA[HP][64];   // 16 KB
    __shared__ unsigned long long sB[HP][64];   // 16 KB
    __shared__ float sP[64];
    __shared__ float sR[64];

    const int tid = threadIdx.x;
    const int nBase = blockIdx.y * 64;
    const int mBase = blockIdx.x * 64;

    const int K1  = g_K1;
    const int mix = g_mix;

    if (tid < 64) sP[tid] = g_P[nBase + tid];
    else          sR[tid - 64] = g_R[mBase + (tid - 64)];

    #pragma unroll
    for (int i = 0; i < 16; ++i) {
        int idx = tid + i * 128;
        int h2 = idx >> 6, l = idx & 63;
        sA[h2][l] = g_aT[h2][nBase + l];
        sB[h2][l] = g_bT[h2][mBase + l];
    }
    __syncthreads();

    const int tx = tid & 15;        // m: 16 cols x 4
    const int ty = tid >> 4;        // n: 8 rows x 8
    const int n0 = ty * 8;
    const int m0 = tx * 4;

    unsigned long long acc[8][4];
    #pragma unroll
    for (int i = 0; i < 8; ++i)
        #pragma unroll
        for (int j = 0; j < 4; ++j)
            acc[i][j] = 0ull;

    // Positive segment [0, K1)
    pipe_segment<+1>(acc, sA, sB, 0, K1, n0, m0);

    // Mixed (+,-) pair at slot K1 (if present)
    if (mix) {
        const unsigned long long sv = pack2(1.0f, -1.0f);
        ulonglong2 A0[4], B0[2];
        tile_load(sA, sB, K1, n0, m0, A0, B0);
        unsigned long long Aa[8] = {A0[0].x, A0[0].y, A0[1].x, A0[1].y,
                                    A0[2].x, A0[2].y, A0[3].x, A0[3].y};
        unsigned long long Bb[4] = {B0[0].x, B0[0].y, B0[1].x, B0[1].y};
        #pragma unroll
        for (int i = 0; i < 8; ++i)
            #pragma unroll
            for (int j = 0; j < 4; ++j)
                stepM(acc[i][j], Aa[i], Bb[j], sv);
    }

    // Negative segment [K1+mix, 32)
    pipe_segment<-1>(acc, sA, sB, K1 + mix, HP, n0, m0);

    // Epilogue: r = acc.lo + acc.hi + P[n] + R[m]
    #pragma unroll
    for (int i = 0; i < 8; ++i) {
        const float pn = sP[n0 + i];
        float r[4];
        #pragma unroll
        for (int j = 0; j < 4; ++j) {
            unsigned long long u = acc[i][j];
            r[j] = (__uint_as_float((unsigned)u) +
                    __uint_as_float((unsigned)(u >> 32))) + (pn + sR[m0 + j]);
        }
        float4 v = make_float4(r[0], r[1], r[2], r[3]);
        *(float4*)&out[(size_t)(nBase + n0 + i) * M + (mBase + m0)] = v;
    }
}

// ---------------------------------------------------------------------------
// Launch
// ---------------------------------------------------------------------------
extern "C" void kernel_launch(void* const* d_in, const int* in_sizes, int n_in,
                              void* d_out, int out_size)
{
    const float* job  = (const float*)d_in[0];
    const float* mac  = (const float*)d_in[1];
    const float* gvec = (const float*)d_in[2];
    const float* Wj   = (const float*)d_in[3];
    const float* bj   = (const float*)d_in[4];
    const float* Wm   = (const float*)d_in[5];
    const float* bm   = (const float*)d_in[6];
    const float* Wg   = (const float*)d_in[7];
    const float* bg   = (const float*)d_in[8];
    const float* W1   = (const float*)d_in[9];
    const float* b1   = (const float*)d_in[10];
    const float* W2   = (const float*)d_in[11];
    const float* b2   = (const float*)d_in[12];
    float* out = (float*)d_out;

    const int N = in_sizes[0];
    const int M = in_sizes[1];

    int rows = N + M;
    precompute_kernel<<<(rows + 7) / 8, 256>>>(
        job, mac, gvec, Wj, bj, Wm, bm, Wg, bg, W1, b1, W2, b2, N, M);

    dim3 grid(M / 64, N / 64);
    qmain_kernel<<<grid, 128>>>(out, N, M);
}